// round 17
// baseline (speedup 1.0000x reference)
#include <cuda_runtime.h>

// Shapes (fixed):
//   x [64,512,32,32] fp32 (HW=1024 contiguous)
//   router_weights [512,16], router_bias [16]
//   bn_gamma/beta [512], ln_gamma/beta [512]
// Output fp32: new_x [64,512] | logits [64,16] | probs [64,16]

#define B_DIM 64
#define C_DIM 512
#define A_DIM 16
#define HW    1024
#define EPSF  1e-5f
#define NBLK1 4096u    // K1: one warp per (b,c) tile, 8 warps/block
#define NBLK2 64u      // K2: one block per batch row

__device__ float    g_sum[B_DIM * C_DIM];   // per-(b,c) spatial sum
__device__ float    g_csum[2][C_DIM];       // per-channel sum   (parity buffered)
__device__ float    g_csq [2][C_DIM];       // per-channel sumsq (parity buffered)
__device__ unsigned g_sp = 0;               // K1 start tickets (monotonic)
__device__ unsigned g_st = 0;               // K2 start tickets (monotonic)

// ---------------------------------------------------------------------------
// K1: per-(b,c) spatial sum + sumsq (proven ~72% DRAM layout) with fused
// per-channel RED atomics. Signals PDL dependents immediately so K2's
// prologue overlaps with the streaming.
// ---------------------------------------------------------------------------
__global__ __launch_bounds__(256) void k_phase1(const float* __restrict__ x)
{
    __shared__ unsigned sstart;
    const int tid  = threadIdx.x;
    const int lane = tid & 31;

    // Allow the dependent grid (k_tail) to launch now; its wait still blocks
    // until this grid fully completes (PTX griddepcontrol semantics).
    asm volatile("griddepcontrol.launch_dependents;");

    if (tid == 0) sstart = atomicAdd(&g_sp, 1u);
    __syncthreads();
    const unsigned par = (sstart / NBLK1) & 1u;   // uniform per launch

    const unsigned tile = blockIdx.x * 8u + (unsigned)(tid >> 5);  // b*512 + c
    const float4* p = reinterpret_cast<const float4*>(x) + (size_t)tile * 256;

    float s = 0.f, q = 0.f;
#pragma unroll
    for (int k = 0; k < 8; ++k) {
        float4 v = p[k * 32 + lane];
        s += v.x + v.y + v.z + v.w;
        q += v.x * v.x + v.y * v.y + v.z * v.z + v.w * v.w;
    }
#pragma unroll
    for (int o = 16; o; o >>= 1) {
        s += __shfl_xor_sync(0xFFFFFFFFu, s, o);
        q += __shfl_xor_sync(0xFFFFFFFFu, q, o);
    }
    if (lane == 0) {
        const unsigned c = tile & (C_DIM - 1u);
        g_sum[tile] = s;
        atomicAdd(&g_csum[par][c], s);            // RED (no return)
        atomicAdd(&g_csq [par][c], q);
    }
}

// ---------------------------------------------------------------------------
// K2: PDL secondary. Prologue (K1-independent): parity ticket, rw weight
// partials, param loads. Then griddepcontrol.wait, then the short dependent
// tail: stats + new_x row + algebraic-LN logits + softmax.
// ---------------------------------------------------------------------------
__global__ __launch_bounds__(256) void k_tail(
    const float* __restrict__ rw,        // [512,16]
    const float* __restrict__ rbias,     // [16]
    const float* __restrict__ bng,
    const float* __restrict__ bnb,
    const float* __restrict__ lng,
    const float* __restrict__ lnb,
    float* __restrict__ out)
{
    __shared__ float nxl [C_DIM];
    __shared__ float part_pa[256], part_sw[256], part_sq[256];
    __shared__ float redG[8], redH[8];
    __shared__ float lsh[A_DIM];
    __shared__ float sG, sHb;
    __shared__ unsigned sstart;

    const int tid  = threadIdx.x;
    const int lane = tid & 31;
    const int wid  = tid >> 5;
    const int b    = blockIdx.x;
    const int c0   = tid, c1 = tid + 256;

    // ---------------- Prologue: everything independent of K1 ----------------
    if (tid == 0) sstart = atomicAdd(&g_st, 1u);

    // Weight-only partials (warms rw in L1 for the pa pass after the wait)
    {
        const int a   = tid & 15;
        const int grp = tid >> 4;
        const float* wp = rw + (grp * 32) * A_DIM + a;
        float sw = 0.f, sq = 0.f;
#pragma unroll
        for (int j = 0; j < 32; ++j) {
            float wv = wp[j * A_DIM];
            sw += wv;
            sq += wv * wv;
        }
        part_sw[tid] = sw;  part_sq[tid] = sq;
    }

    // Per-thread params into registers
    const float bg0 = bng[c0], bg1 = bng[c1];
    const float bb0 = bnb[c0], bb1 = bnb[c1];
    const float lg0 = lng[c0], lg1 = lng[c1];
    const float lb0 = lnb[c0], lb1 = lnb[c1];
    const float rb  = (tid < A_DIM) ? rbias[tid] : 0.f;

    __syncthreads();
    const unsigned par = (sstart / NBLK2) & 1u;   // matches K1's parity

    // ---------------- Wait for K1 grid completion (full visibility) ---------
    asm volatile("griddepcontrol.wait;" ::: "memory");

    // ---------------- Dependent tail ----------------------------------------
    {
        const float invM  = 1.0f / (float)(B_DIM * HW);
        const float invHW = 1.0f / (float)HW;

        float cs0 = g_csum[par][c0], cs1 = g_csum[par][c1];
        float cq0 = g_csq [par][c0], cq1 = g_csq [par][c1];
        float rs0 = g_sum[b * C_DIM + c0], rs1 = g_sum[b * C_DIM + c1];

        float mu0 = cs0 * invM, mu1 = cs1 * invM;
        float r0  = rsqrtf(cq0 * invM - mu0 * mu0 + EPSF);
        float r1  = rsqrtf(cq1 * invM - mu1 * mu1 + EPSF);

        float n0 = bg0 * (rs0 * invHW - mu0) * r0 + bb0;
        float n1 = bg1 * (rs1 * invHW - mu1) * r1 + bb1;
        out[b * C_DIM + c0] = n0;
        out[b * C_DIM + c1] = n1;

        nxl[c0] = n0 * lg0;  nxl[c1] = n1 * lg1;

        float gp = n0 * lg0 + n1 * lg1;
        float hp = n0 * lb0 + n1 * lb1;
#pragma unroll
        for (int o = 16; o; o >>= 1) {
            gp += __shfl_xor_sync(0xFFFFFFFFu, gp, o);
            hp += __shfl_xor_sync(0xFFFFFFFFu, hp, o);
        }
        if (lane == 0) { redG[wid] = gp; redH[wid] = hp; }
    }

    // Zero the OTHER parity's slice for the next replay (its consumers
    // finished in the previous serialized launch).
    if (tid < 8) {
        g_csum[par ^ 1u][b * 8 + tid] = 0.f;
        g_csq [par ^ 1u][b * 8 + tid] = 0.f;
    }
    __syncthreads();
    if (tid == 0) {
        float g = 0.f, h = 0.f;
#pragma unroll
        for (int i = 0; i < 8; ++i) { g += redG[i]; h += redH[i]; }
        sG = g; sHb = h;
    }

    // Dot partials vs normalized row (rw is L1-hot from the prologue)
    {
        const int a   = tid & 15;
        const int grp = tid >> 4;
        const float* wp  = rw  + (grp * 32) * A_DIM + a;
        const float* nlp = nxl + grp * 32;
        float pa = 0.f;
#pragma unroll
        for (int j = 0; j < 32; ++j)
            pa += nlp[j] * wp[j * A_DIM];
        part_pa[tid] = pa;
    }
    __syncthreads();

    // Logits + softmax
    float* logits_out = out + B_DIM * C_DIM;
    float* probs_out  = logits_out + B_DIM * A_DIM;

    if (tid < A_DIM) {
        float P = 0.f, SW = 0.f, SQ = 0.f;
#pragma unroll
        for (int g = 0; g < 16; ++g) {
            P  += part_pa[g * 16 + tid];
            SW += part_sw[g * 16 + tid];
            SQ += part_sq[g * 16 + tid];
        }
        const float invC = 1.0f / (float)C_DIM;
        float m    = SW * invC;
        float rstd = rsqrtf(SQ * invC - m * m + EPSF);
        float logit = rstd * (P - m * sG) + sHb + rb;
        lsh[tid] = logit;
        logits_out[b * A_DIM + tid] = logit;
    }
    __syncthreads();

    if (tid == 0) {
        float mx = lsh[0];
#pragma unroll
        for (int a = 1; a < A_DIM; ++a) mx = fmaxf(mx, lsh[a]);
        float e[A_DIM]; float ssum = 0.f;
#pragma unroll
        for (int a = 0; a < A_DIM; ++a) { e[a] = __expf(lsh[a] - mx); ssum += e[a]; }
        float inv = 1.0f / ssum;
#pragma unroll
        for (int a = 0; a < A_DIM; ++a) probs_out[b * A_DIM + a] = e[a] * inv;
    }
}

extern "C" void kernel_launch(void* const* d_in, const int* in_sizes, int n_in,
                              void* d_out, int out_size)
{
    const float* x        = (const float*)d_in[0];
    const float* rw       = (const float*)d_in[1];
    const float* rbias    = (const float*)d_in[2];
    const float* bn_gamma = (const float*)d_in[3];
    const float* bn_beta  = (const float*)d_in[4];
    const float* ln_gamma = (const float*)d_in[5];
    const float* ln_beta  = (const float*)d_in[6];
    float* out = (float*)d_out;

    k_phase1<<<NBLK1, 256>>>(x);

    // PDL secondary launch; guarded fallback to a plain launch (then the
    // device-side wait degrades to a no-op after normal serialization).
    cudaLaunchConfig_t cfg = {};
    cfg.gridDim  = dim3(NBLK2, 1, 1);
    cfg.blockDim = dim3(256, 1, 1);
    cudaLaunchAttribute attr[1];
    attr[0].id = cudaLaunchAttributeProgrammaticStreamSerialization;
    attr[0].val.programmaticStreamSerializationAllowed = 1;
    cfg.attrs = attr;
    cfg.numAttrs = 1;

    cudaError_t err = cudaLaunchKernelEx(&cfg, k_tail, rw, rbias,
                                         bn_gamma, bn_beta,
                                         ln_gamma, ln_beta, out);
    if (err != cudaSuccess) {
        k_tail<<<NBLK2, 256>>>(rw, rbias, bn_gamma, bn_beta,
                               ln_gamma, ln_beta, out);
    }
}